// round 4
// baseline (speedup 1.0000x reference)
#include <cuda_runtime.h>

#define BB 16
#define NN 2048
#define NCTX 2047
#define EMB 64
#define DIN 160
#define NLAYERS 3
#define ACH 32
#define CHN 64
#define CC 128

typedef unsigned long long ull;

#define PACK2(d, x)      asm("mov.b64 %0, {%1, %1};" : "=l"(d) : "f"(x))
#define UNPACK2(lo, hi, v) asm("mov.b64 {%0, %1}, %2;" : "=f"(lo), "=f"(hi) : "l"(v))
#define FMA2(d, a, b, c) asm("fma.rn.f32x2 %0, %1, %2, %3;" : "=l"(d) : "l"(a), "l"(b), "l"(c))

// Scratch (allocation-free rule: device globals)
__device__ float g_Rpart[BB * ACH * 96 * 32];   // per-(batch,chunk) partial R = [G;C]
__device__ float g_R[BB * 96 * 32];             // reduced R per batch
__device__ float g_P[BB * 64 * 32];             // P[c][j] per batch

// ---------------- Kernel A: R[b] = x[0:96,:2047] @ x[0:32,:2047]^T ----------------
// Transposed smem tile sx[n][96(+pad)] -> contiguous vector LDS, f32x2 FMAs.
extern "C" __global__ void __launch_bounds__(128) kA(const float* __restrict__ x) {
    extern __shared__ float sx[]; // [CHN][100]
    const int b = blockIdx.y, ch = blockIdx.x, tid = threadIdx.x;
    const int n0 = ch * CHN;
    const int count = min(CHN, NCTX - n0);
    const float* xb = x + (size_t)b * DIN * NN;
    for (int i = tid; i < 96 * CHN; i += 128) {
        int r = i >> 6, n = i & 63;
        sx[n * 100 + r] = (n < count) ? xb[r * NN + n0 + n] : 0.f;
    }
    __syncthreads();
    const int tc = tid & 7, tr = tid >> 3;     // tr 0..15
    const int r0 = tr * 6, j0 = tc * 4;
    ull acc[6][2];
#pragma unroll
    for (int rr = 0; rr < 6; rr++) { acc[rr][0] = 0ull; acc[rr][1] = 0ull; }
#pragma unroll 4
    for (int n = 0; n < CHN; n++) {
        const float* row = sx + n * 100;
        float2 a01 = *(const float2*)(row + r0);
        float2 a23 = *(const float2*)(row + r0 + 2);
        float2 a45 = *(const float2*)(row + r0 + 4);
        ulonglong2 bv = *(const ulonglong2*)(row + j0);  // 4 xq cols = 2 pairs
        ull ad[6];
        PACK2(ad[0], a01.x); PACK2(ad[1], a01.y);
        PACK2(ad[2], a23.x); PACK2(ad[3], a23.y);
        PACK2(ad[4], a45.x); PACK2(ad[5], a45.y);
#pragma unroll
        for (int rr = 0; rr < 6; rr++) {
            FMA2(acc[rr][0], ad[rr], bv.x, acc[rr][0]);
            FMA2(acc[rr][1], ad[rr], bv.y, acc[rr][1]);
        }
    }
    float* outp = g_Rpart + (size_t)(b * ACH + ch) * 3072;
#pragma unroll
    for (int rr = 0; rr < 6; rr++) {
        float l0, h0, l1, h1;
        UNPACK2(l0, h0, acc[rr][0]);
        UNPACK2(l1, h1, acc[rr][1]);
        *(float4*)(outp + (r0 + rr) * 32 + j0) = make_float4(l0, h0, l1, h1);
    }
}

// ---------------- Kernel R: reduce 32 partials -> g_R ----------------
extern "C" __global__ void kR() {
    const int b = blockIdx.x;
    const int e = blockIdx.y * 256 + threadIdx.x;   // 0..3071
    const float* p = g_Rpart + (size_t)b * ACH * 3072 + e;
    float s = 0.f;
#pragma unroll
    for (int c = 0; c < ACH; c++) s += p[c * 3072];
    g_R[b * 3072 + e] = s;
}

// ---------------- Kernel B: per-batch tiny algebra -> P ----------------
extern "C" __global__ void kB(const float* __restrict__ alpha,
                              const float* __restrict__ kp_,
                              const float* __restrict__ E,
                              const float* __restrict__ M) {
    extern __shared__ float smb[];
    float* sE   = smb;           // 4096
    float* sM   = sE + 4096;     // 4096
    float* sR   = sM + 4096;     // 3072  (rows 0..31 = G, rows 32..95 = C)
    float* sW   = sR + 3072;     // 2048
    float* sS   = sW + 2048;     // 2048
    float* sT   = sS + 2048;     // 2048
    float* sSum = sT + 2048;     // 2048
    const int b = blockIdx.x, tid = threadIdx.x; // 512 threads
    for (int i = tid; i < 4096; i += 512) { sE[i] = E[i]; sM[i] = M[i]; }
    for (int i = tid; i < 3072; i += 512) sR[i] = g_R[b * 3072 + i];
    for (int i = tid; i < 2048; i += 512) sSum[i] = 0.f;
    __syncthreads();

    const int i0 = tid >> 3;
    const int j0 = (tid & 7) * 4;
    const float* sC = sR + 32 * 32;

    // W0 = E @ C
    {
        float a0 = 0, a1 = 0, a2 = 0, a3 = 0;
#pragma unroll
        for (int k = 0; k < 64; k++) {
            float e = sE[i0 * 64 + k];
            float4 cv = *(const float4*)(sC + k * 32 + j0);
            a0 += e * cv.x; a1 += e * cv.y; a2 += e * cv.z; a3 += e * cv.w;
        }
        *(float4*)(sW + i0 * 32 + j0) = make_float4(a0, a1, a2, a3);
    }
    __syncthreads();

    const float kp = kp_[0];
    for (int l = 0; l < NLAYERS; l++) {
        float sc = kp * alpha[l * EMB + i0] * (1.0f / (float)NCTX);
        {
            float4 wv = *(const float4*)(sW + i0 * 32 + j0);
            float4 sv = make_float4(sc * wv.x, sc * wv.y, sc * wv.z, sc * wv.w);
            *(float4*)(sS + i0 * 32 + j0) = sv;
            float4 su = *(const float4*)(sSum + i0 * 32 + j0);
            su.x += sv.x; su.y += sv.y; su.z += sv.z; su.w += sv.w;
            *(float4*)(sSum + i0 * 32 + j0) = su;
        }
        __syncthreads();
        if (l < NLAYERS - 1) {
            // T = M @ S
            float a0 = 0, a1 = 0, a2 = 0, a3 = 0;
#pragma unroll
            for (int k = 0; k < 64; k++) {
                float m = sM[i0 * 64 + k];
                float4 sv = *(const float4*)(sS + k * 32 + j0);
                a0 += m * sv.x; a1 += m * sv.y; a2 += m * sv.z; a3 += m * sv.w;
            }
            *(float4*)(sT + i0 * 32 + j0) = make_float4(a0, a1, a2, a3);
            __syncthreads();
            // W += T @ G
            a0 = 0; a1 = 0; a2 = 0; a3 = 0;
#pragma unroll
            for (int p = 0; p < 32; p++) {
                float t = sT[i0 * 32 + p];
                float4 gv = *(const float4*)(sR + p * 32 + j0);
                a0 += t * gv.x; a1 += t * gv.y; a2 += t * gv.z; a3 += t * gv.w;
            }
            float4 wv = *(const float4*)(sW + i0 * 32 + j0);
            wv.x += a0; wv.y += a1; wv.z += a2; wv.w += a3;
            *(float4*)(sW + i0 * 32 + j0) = wv;
            __syncthreads();
        }
    }
    // P[c][j] = sum_d E[d][c] * Sum[d][j]  (c = i0)
    {
        float a0 = 0, a1 = 0, a2 = 0, a3 = 0;
#pragma unroll
        for (int d = 0; d < 64; d++) {
            float e = sE[d * 64 + i0];
            float4 sv = *(const float4*)(sSum + d * 32 + j0);
            a0 += e * sv.x; a1 += e * sv.y; a2 += e * sv.z; a3 += e * sv.w;
        }
        *(float4*)(g_P + (size_t)(b * 64 + i0) * 32 + j0) = make_float4(a0, a1, a2, a3);
    }
}

// ---------------- Kernel C: logits = U^T @ V (f32x2), softmax (shfl), direct stores ----
extern "C" __global__ void __launch_bounds__(128) kC(const float* __restrict__ x,
                                                     const float* __restrict__ E,
                                                     float* __restrict__ out) {
    extern __shared__ float smc[];
    float* sU = smc;            // 96 x 68 (stride pad)
    float* sV = sU + 96 * 68;   // 96 x 132
    const int b = blockIdx.y, chn = blockIdx.x, tid = threadIdx.x;
    const int n0 = chn * CC;
    const float* xb = x + (size_t)b * DIN * NN;
    // U[k][c]: k<64 -> E[k][c]; k=64+j -> P[c][j]
    for (int i = tid; i < 96 * 64; i += 128) {
        int k = i >> 6, c = i & 63;
        sU[k * 68 + c] = (k < 64) ? E[i] : g_P[(size_t)(b * 64 + c) * 32 + (k - 64)];
    }
    // V[k][n]: k<64 -> f0 row (96+k); k=64+j -> xq row j
    for (int i = tid; i < 96 * CC; i += 128) {
        int k = i >> 7, n = i & 127;
        int row = (k < 64) ? (96 + k) : (k - 64);
        sV[k * 132 + n] = xb[row * NN + n0 + n];
    }
    __syncthreads();
    const int tc = tid & 7, tn = tid >> 3;   // tn 0..15
    const int c4 = tc * 4, nb = tn * 8;
    // classes: c4..c4+3 and c4+32..c4+35 ; cols nb..nb+7 (4 pairs)
    ull acc[8][4];
#pragma unroll
    for (int a = 0; a < 8; a++)
#pragma unroll
        for (int p = 0; p < 4; p++) acc[a][p] = 0ull;
#pragma unroll 2
    for (int k = 0; k < 96; k++) {
        float4 u0 = *(const float4*)(sU + k * 68 + c4);
        float4 u1 = *(const float4*)(sU + k * 68 + 32 + c4);
        ulonglong2 v0 = *(const ulonglong2*)(sV + k * 132 + nb);
        ulonglong2 v1 = *(const ulonglong2*)(sV + k * 132 + nb + 4);
        ull vp0 = v0.x, vp1 = v0.y, vp2 = v1.x, vp3 = v1.y;
        ull ad[8];
        PACK2(ad[0], u0.x); PACK2(ad[1], u0.y); PACK2(ad[2], u0.z); PACK2(ad[3], u0.w);
        PACK2(ad[4], u1.x); PACK2(ad[5], u1.y); PACK2(ad[6], u1.z); PACK2(ad[7], u1.w);
#pragma unroll
        for (int a = 0; a < 8; a++) {
            FMA2(acc[a][0], ad[a], vp0, acc[a][0]);
            FMA2(acc[a][1], ad[a], vp1, acc[a][1]);
            FMA2(acc[a][2], ad[a], vp2, acc[a][2]);
            FMA2(acc[a][3], ad[a], vp3, acc[a][3]);
        }
    }
    // unpack: fl[class 0..7][col 0..7]
    float fl[8][8];
#pragma unroll
    for (int a = 0; a < 8; a++)
#pragma unroll
        for (int p = 0; p < 4; p++)
            UNPACK2(fl[a][2 * p], fl[a][2 * p + 1], acc[a][p]);

    float* gl = out + ((size_t)(b * NN + n0)) * 64;
    float* gp = gl + (size_t)BB * NN * 64;
#pragma unroll
    for (int q = 0; q < 8; q++) {
        const size_t col = (size_t)(nb + q) * 64;
        *(float4*)(gl + col + c4)      = make_float4(fl[0][q], fl[1][q], fl[2][q], fl[3][q]);
        *(float4*)(gl + col + 32 + c4) = make_float4(fl[4][q], fl[5][q], fl[6][q], fl[7][q]);
        float m = fl[0][q];
#pragma unroll
        for (int a = 1; a < 8; a++) m = fmaxf(m, fl[a][q]);
#pragma unroll
        for (int off = 1; off < 8; off <<= 1)
            m = fmaxf(m, __shfl_xor_sync(0xffffffffu, m, off));
        float e[8]; float s = 0.f;
#pragma unroll
        for (int a = 0; a < 8; a++) { e[a] = __expf(fl[a][q] - m); s += e[a]; }
#pragma unroll
        for (int off = 1; off < 8; off <<= 1)
            s += __shfl_xor_sync(0xffffffffu, s, off);
        float inv = __frcp_rn(s);
        *(float4*)(gp + col + c4)      = make_float4(e[0] * inv, e[1] * inv, e[2] * inv, e[3] * inv);
        *(float4*)(gp + col + 32 + c4) = make_float4(e[4] * inv, e[5] * inv, e[6] * inv, e[7] * inv);
    }
}

extern "C" void kernel_launch(void* const* d_in, const int* in_sizes, int n_in,
                              void* d_out, int out_size) {
    const float* x     = (const float*)d_in[0];
    const float* alpha = (const float*)d_in[1];
    const float* kp    = (const float*)d_in[2];
    const float* E     = (const float*)d_in[3];
    const float* M     = (const float*)d_in[4];
    float* out = (float*)d_out;

    const int smemA = CHN * 100 * 4;                // 25,600 B
    const int smemB = (4096*2 + 3072 + 2048*4) * 4; // 77,824 B
    const int smemC = (96 * 68 + 96 * 132) * 4;     // 76,800 B
    cudaFuncSetAttribute(kA, cudaFuncAttributeMaxDynamicSharedMemorySize, smemA);
    cudaFuncSetAttribute(kB, cudaFuncAttributeMaxDynamicSharedMemorySize, smemB);
    cudaFuncSetAttribute(kC, cudaFuncAttributeMaxDynamicSharedMemorySize, smemC);

    kA<<<dim3(ACH, BB), 128, smemA>>>(x);
    kR<<<dim3(BB, 12), 256>>>();
    kB<<<BB, 512, smemB>>>(alpha, kp, E, M);
    kC<<<dim3(NN / CC, BB), 128, smemC>>>(x, E, out);
}

// round 5
// speedup vs baseline: 1.0359x; 1.0359x over previous
#include <cuda_runtime.h>

#define BB 16
#define NN 2048
#define NCTX 2047
#define EMB 64
#define DIN 160
#define NLAYERS 3
#define ACH 16
#define CHN 128
#define CC 128

typedef unsigned long long ull;

#define PACK2(d, x)      asm("mov.b64 %0, {%1, %1};" : "=l"(d) : "f"(x))
#define UNPACK2(lo, hi, v) asm("mov.b64 {%0, %1}, %2;" : "=f"(lo), "=f"(hi) : "l"(v))
#define FMA2(d, a, b, c) asm("fma.rn.f32x2 %0, %1, %2, %3;" : "=l"(d) : "l"(a), "l"(b), "l"(c))

// Scratch (allocation-free rule: device globals)
__device__ float g_Rpart[BB * ACH * 96 * 32];   // per-(batch,chunk) partial R = [G;C]
__device__ float g_R[BB * 96 * 32];             // reduced R per batch
__device__ float g_P[BB * 64 * 32];             // P[c][j] per batch

// ---------------- Kernel A: R[b] = x[0:96,:2047] @ x[0:32,:2047]^T ----------------
// Transposed tile sx[n][96] stride 98; rows packed as f32x2 pairs; 256 thr, 6x2/thread.
extern "C" __global__ void __launch_bounds__(256) kA(const float* __restrict__ x) {
    extern __shared__ float sx[]; // [CHN][98]
    const int b = blockIdx.y, ch = blockIdx.x, tid = threadIdx.x;
    const int n0 = ch * CHN;
    const int count = min(CHN, NCTX - n0);
    const float* xb = x + (size_t)b * DIN * NN;
    for (int i = tid; i < 96 * CHN; i += 256) {
        int r = i >> 7, n = i & 127;
        sx[n * 98 + r] = (n < count) ? xb[r * NN + n0 + n] : 0.f;
    }
    __syncthreads();
    const int tc = tid & 15, tr = tid >> 4;   // tr 0..15
    const int r0 = tr * 6, j0 = tc * 2;
    ull acc[3][2];
#pragma unroll
    for (int p = 0; p < 3; p++) { acc[p][0] = 0ull; acc[p][1] = 0ull; }
#pragma unroll 4
    for (int n = 0; n < CHN; n++) {
        const float* row = sx + n * 98;
        ull a0 = *(const ull*)(row + r0);       // rows r0, r0+1
        ull a1 = *(const ull*)(row + r0 + 2);
        ull a2 = *(const ull*)(row + r0 + 4);
        float2 q = *(const float2*)(row + j0);  // xq cols j0, j0+1 (broadcast-free)
        ull q0, q1;
        PACK2(q0, q.x); PACK2(q1, q.y);
        FMA2(acc[0][0], a0, q0, acc[0][0]); FMA2(acc[0][1], a0, q1, acc[0][1]);
        FMA2(acc[1][0], a1, q0, acc[1][0]); FMA2(acc[1][1], a1, q1, acc[1][1]);
        FMA2(acc[2][0], a2, q0, acc[2][0]); FMA2(acc[2][1], a2, q1, acc[2][1]);
    }
    float* outp = g_Rpart + (size_t)(b * ACH + ch) * 3072;
#pragma unroll
    for (int p = 0; p < 3; p++) {
        float l0, h0, l1, h1;
        UNPACK2(l0, h0, acc[p][0]);   // rows r0+2p, r0+2p+1 @ col j0
        UNPACK2(l1, h1, acc[p][1]);   // @ col j0+1
        *(float2*)(outp + (r0 + 2 * p) * 32 + j0)     = make_float2(l0, l1);
        *(float2*)(outp + (r0 + 2 * p + 1) * 32 + j0) = make_float2(h0, h1);
    }
}

// ---------------- Kernel R: reduce ACH partials -> g_R ----------------
extern "C" __global__ void kR() {
    const int b = blockIdx.x;
    const int e = blockIdx.y * 256 + threadIdx.x;   // 0..3071
    const float* p = g_Rpart + (size_t)b * ACH * 3072 + e;
    float s = 0.f;
#pragma unroll
    for (int c = 0; c < ACH; c++) s += p[c * 3072];
    g_R[b * 3072 + e] = s;
}

// ---------------- Kernel B: per-batch tiny algebra -> P ----------------
extern "C" __global__ void kB(const float* __restrict__ alpha,
                              const float* __restrict__ kp_,
                              const float* __restrict__ E,
                              const float* __restrict__ M) {
    extern __shared__ float smb[];
    float* sE   = smb;           // 4096
    float* sM   = sE + 4096;     // 4096
    float* sR   = sM + 4096;     // 3072  (rows 0..31 = G, rows 32..95 = C)
    float* sW   = sR + 3072;     // 2048
    float* sS   = sW + 2048;     // 2048
    float* sT   = sS + 2048;     // 2048
    float* sSum = sT + 2048;     // 2048
    const int b = blockIdx.x, tid = threadIdx.x; // 512 threads
    for (int i = tid; i < 4096; i += 512) { sE[i] = E[i]; sM[i] = M[i]; }
    for (int i = tid; i < 3072; i += 512) sR[i] = g_R[b * 3072 + i];
    for (int i = tid; i < 2048; i += 512) sSum[i] = 0.f;
    __syncthreads();

    const int i0 = tid >> 3;
    const int j0 = (tid & 7) * 4;
    const float* sC = sR + 32 * 32;

    // W0 = E @ C
    {
        float a0 = 0, a1 = 0, a2 = 0, a3 = 0;
#pragma unroll
        for (int k = 0; k < 64; k++) {
            float e = sE[i0 * 64 + k];
            float4 cv = *(const float4*)(sC + k * 32 + j0);
            a0 += e * cv.x; a1 += e * cv.y; a2 += e * cv.z; a3 += e * cv.w;
        }
        *(float4*)(sW + i0 * 32 + j0) = make_float4(a0, a1, a2, a3);
    }
    __syncthreads();

    const float kp = kp_[0];
    for (int l = 0; l < NLAYERS; l++) {
        float sc = kp * alpha[l * EMB + i0] * (1.0f / (float)NCTX);
        {
            float4 wv = *(const float4*)(sW + i0 * 32 + j0);
            float4 sv = make_float4(sc * wv.x, sc * wv.y, sc * wv.z, sc * wv.w);
            *(float4*)(sS + i0 * 32 + j0) = sv;
            float4 su = *(const float4*)(sSum + i0 * 32 + j0);
            su.x += sv.x; su.y += sv.y; su.z += sv.z; su.w += sv.w;
            *(float4*)(sSum + i0 * 32 + j0) = su;
        }
        __syncthreads();
        if (l < NLAYERS - 1) {
            // T = M @ S
            float a0 = 0, a1 = 0, a2 = 0, a3 = 0;
#pragma unroll
            for (int k = 0; k < 64; k++) {
                float m = sM[i0 * 64 + k];
                float4 sv = *(const float4*)(sS + k * 32 + j0);
                a0 += m * sv.x; a1 += m * sv.y; a2 += m * sv.z; a3 += m * sv.w;
            }
            *(float4*)(sT + i0 * 32 + j0) = make_float4(a0, a1, a2, a3);
            __syncthreads();
            // W += T @ G
            a0 = 0; a1 = 0; a2 = 0; a3 = 0;
#pragma unroll
            for (int p = 0; p < 32; p++) {
                float t = sT[i0 * 32 + p];
                float4 gv = *(const float4*)(sR + p * 32 + j0);
                a0 += t * gv.x; a1 += t * gv.y; a2 += t * gv.z; a3 += t * gv.w;
            }
            float4 wv = *(const float4*)(sW + i0 * 32 + j0);
            wv.x += a0; wv.y += a1; wv.z += a2; wv.w += a3;
            *(float4*)(sW + i0 * 32 + j0) = wv;
            __syncthreads();
        }
    }
    // P[c][j] = sum_d E[d][c] * Sum[d][j]  (c = i0)
    {
        float a0 = 0, a1 = 0, a2 = 0, a3 = 0;
#pragma unroll
        for (int d = 0; d < 64; d++) {
            float e = sE[d * 64 + i0];
            float4 sv = *(const float4*)(sSum + d * 32 + j0);
            a0 += e * sv.x; a1 += e * sv.y; a2 += e * sv.z; a3 += e * sv.w;
        }
        *(float4*)(g_P + (size_t)(b * 64 + i0) * 32 + j0) = make_float4(a0, a1, a2, a3);
    }
}

// ---------------- Kernel C: logits = U^T @ V (f32x2), softmax (shfl), direct stores ----
extern "C" __global__ void __launch_bounds__(256) kC(const float* __restrict__ x,
                                                     const float* __restrict__ E,
                                                     float* __restrict__ out) {
    extern __shared__ float smc[];
    float* sU = smc;            // 96 x 64
    float* sV = sU + 96 * 64;   // 96 x 128
    const int b = blockIdx.y, chn = blockIdx.x, tid = threadIdx.x;
    const int n0 = chn * CC;
    const float* xb = x + (size_t)b * DIN * NN;
    // U[k][c]: k<64 -> E[k][c]; k=64+j -> P[c][j]
    for (int i = tid; i < 96 * 64; i += 256) {
        int k = i >> 6, c = i & 63;
        sU[i] = (k < 64) ? E[i] : g_P[(size_t)(b * 64 + c) * 32 + (k - 64)];
    }
    // V[k][n]: k<64 -> f0 row (96+k); k=64+j -> xq row j
    for (int i = tid; i < 96 * CC; i += 256) {
        int k = i >> 7, n = i & 127;
        int row = (k < 64) ? (96 + k) : (k - 64);
        sV[i] = xb[row * NN + n0 + n];
    }
    __syncthreads();
    const int tc = tid & 15, tn = tid >> 4;   // tn 0..15
    const int c0 = tc * 4, nb = tn * 8;
    // 4 classes x 8 cols per thread
    ull acc[4][4];
#pragma unroll
    for (int a = 0; a < 4; a++)
#pragma unroll
        for (int p = 0; p < 4; p++) acc[a][p] = 0ull;
#pragma unroll 2
    for (int k = 0; k < 96; k++) {
        float4 u = *(const float4*)(sU + k * 64 + c0);
        ulonglong2 v0 = *(const ulonglong2*)(sV + k * 128 + nb);
        ulonglong2 v1 = *(const ulonglong2*)(sV + k * 128 + nb + 4);
        ull ad[4];
        PACK2(ad[0], u.x); PACK2(ad[1], u.y); PACK2(ad[2], u.z); PACK2(ad[3], u.w);
#pragma unroll
        for (int a = 0; a < 4; a++) {
            FMA2(acc[a][0], ad[a], v0.x, acc[a][0]);
            FMA2(acc[a][1], ad[a], v0.y, acc[a][1]);
            FMA2(acc[a][2], ad[a], v1.x, acc[a][2]);
            FMA2(acc[a][3], ad[a], v1.y, acc[a][3]);
        }
    }
    // unpack: fl[class 0..3][col 0..7]
    float fl[4][8];
#pragma unroll
    for (int a = 0; a < 4; a++)
#pragma unroll
        for (int p = 0; p < 4; p++)
            UNPACK2(fl[a][2 * p], fl[a][2 * p + 1], acc[a][p]);

    float* gl = out + ((size_t)(b * NN + n0)) * 64;
    float* gp = gl + (size_t)BB * NN * 64;
#pragma unroll
    for (int q = 0; q < 8; q++) {
        const size_t col = (size_t)(nb + q) * 64;
        *(float4*)(gl + col + c0) = make_float4(fl[0][q], fl[1][q], fl[2][q], fl[3][q]);
        float m = fmaxf(fmaxf(fl[0][q], fl[1][q]), fmaxf(fl[2][q], fl[3][q]));
#pragma unroll
        for (int off = 1; off < 16; off <<= 1)
            m = fmaxf(m, __shfl_xor_sync(0xffffffffu, m, off));
        float e0 = __expf(fl[0][q] - m);
        float e1 = __expf(fl[1][q] - m);
        float e2 = __expf(fl[2][q] - m);
        float e3 = __expf(fl[3][q] - m);
        float s = e0 + e1 + e2 + e3;
#pragma unroll
        for (int off = 1; off < 16; off <<= 1)
            s += __shfl_xor_sync(0xffffffffu, s, off);
        float inv = __frcp_rn(s);
        *(float4*)(gp + col + c0) = make_float4(e0 * inv, e1 * inv, e2 * inv, e3 * inv);
    }
}

extern "C" void kernel_launch(void* const* d_in, const int* in_sizes, int n_in,
                              void* d_out, int out_size) {
    const float* x     = (const float*)d_in[0];
    const float* alpha = (const float*)d_in[1];
    const float* kp    = (const float*)d_in[2];
    const float* E     = (const float*)d_in[3];
    const float* M     = (const float*)d_in[4];
    float* out = (float*)d_out;

    const int smemA = CHN * 98 * 4;                 // 50,176 B
    const int smemB = (4096*2 + 3072 + 2048*4) * 4; // 77,824 B
    const int smemC = (96 * 64 + 96 * 128) * 4;     // 73,728 B
    cudaFuncSetAttribute(kA, cudaFuncAttributeMaxDynamicSharedMemorySize, smemA);
    cudaFuncSetAttribute(kB, cudaFuncAttributeMaxDynamicSharedMemorySize, smemB);
    cudaFuncSetAttribute(kC, cudaFuncAttributeMaxDynamicSharedMemorySize, smemC);

    kA<<<dim3(ACH, BB), 256, smemA>>>(x);
    kR<<<dim3(BB, 12), 256>>>();
    kB<<<BB, 512, smemB>>>(alpha, kp, E, M);
    kC<<<dim3(NN / CC, BB), 256, smemC>>>(x, E, out);
}